// round 12
// baseline (speedup 1.0000x reference)
#include <cuda_runtime.h>
#include <cuda_bf16.h>
#include <cstdint>

// RoPE2D encoder: output = [cos_2d (HW x 128) ; sin_2d (HW x 128)], fp32.
// H = W = 512, DIM = 128. Channels [0,64) depend only on x, [64,128) only on y.
// Converged design: single fused kernel at the LTS/HBM write-path floor
// (~7.0 TB/s measured). Warp = fixed half (cos or sin) + 8 consecutive
// positions (same y). Lane q = float4 chunk: q<16 x-half (rotates by f per
// row), q>=16 y-half (identity rotation). sincosf once in the prologue, then
// an angle-addition recurrence; c/s pre-swapped by `which` so the store loop
// is pure FFMA + STG.128. 512-thread blocks to halve CTA dispatch count.

#define RP_H 512
#define RP_W 512
#define RP_HW (RP_H * RP_W)
#define ROWS_PER_WARP 8

__global__ void __launch_bounds__(512) rope2d_fused(float4* __restrict__ out,
                                                    const float* __restrict__ inv_freq_x,
                                                    const float* __restrict__ inv_freq_y) {
    unsigned warp_in_block = threadIdx.x >> 5;
    unsigned q             = threadIdx.x & 31u;
    unsigned gw    = blockIdx.x * 16u + warp_in_block;  // 0..65535
    unsigned which = gw >> 15;                          // 0 = cos, 1 = sin
    unsigned rp    = gw & 32767u;
    unsigned p0    = rp * ROWS_PER_WARP;
    unsigned y     = p0 >> 9;
    unsigned x0    = p0 & 511u;

    bool is_x = (q < 16u);

    // channels 4*(q mod 16)+j ; freq index mod 32 -> aligned float4 at q&7.
    const float4* tf = reinterpret_cast<const float4*>(is_x ? inv_freq_x : inv_freq_y);
    float4 f4 = __ldg(tf + (q & 7u));
    float fr[4] = {f4.x, f4.y, f4.z, f4.w};

    float pos  = is_x ? (float)x0 : (float)y;
    float step = is_x ? 1.0f : 0.0f;          // y-lanes: identity rotation

    // a[] = emitted value (cos or sin per `which`), b[] = companion.
    //   emit cos: a=cos,b=sin, sign=-1 ; emit sin: a=sin,b=cos, sign=+1
    //   a' = a*cf + sign*b*sf ; b' = b*cf - sign*a*sf   (sign folded into sf)
    float a[4], b[4], cf[4], sf[4];
    float sign = which ? 1.0f : -1.0f;
    #pragma unroll
    for (int j = 0; j < 4; j++) {
        float cc, ss;
        sincosf(pos * fr[j], &ss, &cc);
        a[j] = which ? ss : cc;
        b[j] = which ? cc : ss;
        sincosf(step * fr[j], &sf[j], &cf[j]);
        sf[j] *= sign;
    }

    float4* row = out + (size_t)which * (RP_HW * 32u) + (size_t)p0 * 32u + q;

    #pragma unroll
    for (int i = 0; i < ROWS_PER_WARP; i++) {
        float4 val;
        val.x = a[0]; val.y = a[1]; val.z = a[2]; val.w = a[3];
        __stcs(row + (size_t)i * 32u, val);   // streaming 512B/warp store

        if (i < ROWS_PER_WARP - 1) {
            #pragma unroll
            for (int j = 0; j < 4; j++) {
                float an = fmaf(a[j], cf[j],  b[j] * sf[j]);
                float bn = fmaf(b[j], cf[j], -a[j] * sf[j]);
                a[j] = an;
                b[j] = bn;
            }
        }
    }
}

extern "C" void kernel_launch(void* const* d_in, const int* in_sizes, int n_in,
                              void* d_out, int out_size) {
    const float* inv_freq_x = (const float*)d_in[1];
    const float* inv_freq_y = (const float*)d_in[2];
    float4* out = (float4*)d_out;

    // 65536 warps = 2 (which) x 32768 row-groups; 16 warps/block -> 4096 blocks
    rope2d_fused<<<4096, 512>>>(out, inv_freq_x, inv_freq_y);
}